// round 11
// baseline (speedup 1.0000x reference)
#include <cuda_runtime.h>
#include <cuda_bf16.h>
#include <math.h>

#define B_    2
#define NH_   4
#define T_    8
#define H_    14
#define W_    14
#define N_    1568
#define DIM_  384
#define HD_   96
#define BH_   (B_*NH_)
#define M_    (B_*N_)
#define EPS_  1e-6f
#define SCALE_ 0.1020620726159657f     // 96^-0.5
#define LOG2E_ 1.4426950408889634f
#define KSC_   0.1472444463f           // SCALE_ * LOG2E_

typedef unsigned long long ull;

__device__ __forceinline__ unsigned cvt_tf32(float f) {
    unsigned r;
    asm("cvt.rna.tf32.f32 %0, %1;" : "=r"(r) : "f"(f));
    return r;
}
__device__ __forceinline__ float ex2f(float x) {
    float r;
    asm("ex2.approx.ftz.f32 %0, %1;" : "=f"(r) : "f"(x));
    return r;
}
// tf32 mma m16n8k8: D += A*B, A row-major 16x8, B "col" ([n][k]) 8x8
__device__ __forceinline__ void mma_tf32(float c[4], unsigned a0, unsigned a1,
                                         unsigned a2, unsigned a3,
                                         unsigned b0, unsigned b1) {
    asm("mma.sync.aligned.m16n8k8.row.col.f32.tf32.tf32.f32 "
        "{%0,%1,%2,%3}, {%4,%5,%6,%7}, {%8,%9}, {%0,%1,%2,%3};"
        : "+f"(c[0]), "+f"(c[1]), "+f"(c[2]), "+f"(c[3])
        : "r"(a0), "r"(a1), "r"(a2), "r"(a3), "r"(b0), "r"(b1));
}

// ---------------- scratch ---------------------------------------------------
__device__ float g_q_raw[BH_ * N_ * HD_];
__device__ float g_k_raw[BH_ * N_ * HD_];
__device__ float g_v_raw[BH_ * N_ * HD_];
__device__ float g_q[BH_ * N_ * HD_];
__device__ float g_k[BH_ * N_ * HD_];
__device__ float g_v[BH_ * N_ * HD_];
__device__ float g_ctx[B_ * N_ * DIM_];

// ------- 64x64 NT GEMM core, tf32 MMA, double-buffered smem ----------------
__device__ __forceinline__ void mma_nt64(const float* __restrict__ A,
                                         const float* __restrict__ Bw,
                                         int K, int m0, int n0,
                                         int wm, int wn, int g, int t,
                                         int tid, float acc[4][4]) {
    __shared__ unsigned Xs[2][64 * 36];
    __shared__ unsigned Ws[2][64 * 36];
    const int r0 = tid >> 3, c40 = tid & 7;
    const int r1 = (tid + 256) >> 3, c41 = tid & 7;
    const int ra = 16 * wm + g;

    float4 pa0 = *(const float4*)&A[(size_t)(m0 + r0) * K + c40 * 4];
    float4 pb0 = *(const float4*)&Bw[(size_t)(n0 + r0) * K + c40 * 4];
    float4 pa1 = *(const float4*)&A[(size_t)(m0 + r1) * K + c41 * 4];
    float4 pb1 = *(const float4*)&Bw[(size_t)(n0 + r1) * K + c41 * 4];
    #define ST_TF32(dst, v) do { uint4 _u; _u.x = cvt_tf32((v).x); _u.y = cvt_tf32((v).y); \
        _u.z = cvt_tf32((v).z); _u.w = cvt_tf32((v).w); *(uint4*)(dst) = _u; } while (0)
    ST_TF32(&Xs[0][r0 * 36 + c40 * 4], pa0);
    ST_TF32(&Ws[0][r0 * 36 + c40 * 4], pb0);
    ST_TF32(&Xs[0][r1 * 36 + c41 * 4], pa1);
    ST_TF32(&Ws[0][r1 * 36 + c41 * 4], pb1);
    __syncthreads();

    int p = 0;
    for (int k0 = 0; k0 < K; k0 += 32) {
        if (k0 + 32 < K) {
            pa0 = *(const float4*)&A[(size_t)(m0 + r0) * K + k0 + 32 + c40 * 4];
            pb0 = *(const float4*)&Bw[(size_t)(n0 + r0) * K + k0 + 32 + c40 * 4];
            pa1 = *(const float4*)&A[(size_t)(m0 + r1) * K + k0 + 32 + c41 * 4];
            pb1 = *(const float4*)&Bw[(size_t)(n0 + r1) * K + k0 + 32 + c41 * 4];
        }
        #pragma unroll
        for (int ks = 0; ks < 4; ks++) {
            int kk = ks * 8;
            unsigned a0 = Xs[p][ra * 36 + kk + t];
            unsigned a1 = Xs[p][(ra + 8) * 36 + kk + t];
            unsigned a2 = Xs[p][ra * 36 + kk + t + 4];
            unsigned a3 = Xs[p][(ra + 8) * 36 + kk + t + 4];
            #pragma unroll
            for (int u = 0; u < 4; u++) {
                int nr = 32 * wn + 8 * u + g;
                unsigned b0 = Ws[p][nr * 36 + kk + t];
                unsigned b1 = Ws[p][nr * 36 + kk + t + 4];
                mma_tf32(acc[u], a0, a1, a2, a3, b0, b1);
            }
        }
        if (k0 + 32 < K) {
            ST_TF32(&Xs[1 - p][r0 * 36 + c40 * 4], pa0);
            ST_TF32(&Ws[1 - p][r0 * 36 + c40 * 4], pb0);
            ST_TF32(&Xs[1 - p][r1 * 36 + c41 * 4], pa1);
            ST_TF32(&Ws[1 - p][r1 * 36 + c41 * 4], pb1);
            __syncthreads();
            p ^= 1;
        }
    }
    #undef ST_TF32
}

// ---------------- K1: QKV projection (tf32 MMA) -----------------------------
__global__ void __launch_bounds__(256, 2) k_qkv(const float* __restrict__ x,
                                                const float* __restrict__ qkv_w) {
    int n0 = blockIdx.x * 64, m0 = blockIdx.y * 64;
    int tid = threadIdx.x;
    int wid = tid >> 5, lane = tid & 31;
    int wm = wid >> 1, wn = wid & 1;
    int g = lane >> 2, t = lane & 3;
    float acc[4][4] = {};
    mma_nt64(x, qkv_w, DIM_, m0, n0, wm, wn, g, t, tid, acc);

    int ra = 16 * wm + g;
    #pragma unroll
    for (int half = 0; half < 2; half++) {
        int m = m0 + ra + 8 * half;
        int b = m / N_, n = m - b * N_;
        #pragma unroll
        for (int u = 0; u < 4; u++) {
            int o = n0 + 32 * wn + 8 * u + 2 * t;
            int s = o / DIM_;
            int rem = o - s * DIM_;
            int head = rem / HD_;
            int c = rem - head * HD_;
            float* dst = (s == 0) ? g_q_raw : (s == 1) ? g_k_raw : g_v_raw;
            float2 v = make_float2(acc[u][2 * half], acc[u][2 * half + 1]);
            *(float2*)&dst[((size_t)(b * NH_ + head) * N_ + n) * HD_ + c] = v;
        }
    }
}

// ---------------- K2: conv3x3x3 + LayerNorm, warp per token ---------------
__global__ void __launch_bounds__(128) k_conv_ln(
        const float* __restrict__ wq, const float* __restrict__ wk,
        const float* __restrict__ wv,
        const float* __restrict__ gq, const float* __restrict__ bq,
        const float* __restrict__ gk, const float* __restrict__ bk,
        const float* __restrict__ gv, const float* __restrict__ bv) {
    int gid = blockIdx.x * 4 + (threadIdx.x >> 5);
    int lane = threadIdx.x & 31;
    int z = gid / (BH_ * N_);
    int rem0 = gid - z * (BH_ * N_);
    int bh = rem0 / N_;
    int n = rem0 - bh * N_;
    const float* inb  = (z == 0) ? g_q_raw : (z == 1) ? g_k_raw : g_v_raw;
    float*       outb = (z == 0) ? g_q     : (z == 1) ? g_k     : g_v;
    const float* wt    = (z == 0) ? wq : (z == 1) ? wk : wv;
    const float* gamma = (z == 0) ? gq : (z == 1) ? gk : gv;
    const float* beta  = (z == 0) ? bq : (z == 1) ? bk : bv;

    int tt = n / (H_ * W_);
    int rem = n - tt * (H_ * W_);
    int hh = rem / W_, ww = rem - (rem / W_) * W_;

    float val[3] = {0.f, 0.f, 0.f};
    #pragma unroll
    for (int dt = -1; dt <= 1; dt++) {
        int t2 = tt + dt;
        if (t2 < 0 || t2 >= T_) continue;
        #pragma unroll
        for (int dh = -1; dh <= 1; dh++) {
            int h2 = hh + dh;
            if (h2 < 0 || h2 >= H_) continue;
            #pragma unroll
            for (int dw = -1; dw <= 1; dw++) {
                int w2 = ww + dw;
                if (w2 < 0 || w2 >= W_) continue;
                int n2 = (t2 * H_ + h2) * W_ + w2;
                const float* src = &inb[((size_t)bh * N_ + n2) * HD_];
                int tap = (dt + 1) * 9 + (dh + 1) * 3 + (dw + 1);
                #pragma unroll
                for (int p = 0; p < 3; p++) {
                    int c = lane + 32 * p;
                    val[p] += wt[c * 27 + tap] * src[c];
                }
            }
        }
    }
    float s = val[0] + val[1] + val[2];
    float q = val[0]*val[0] + val[1]*val[1] + val[2]*val[2];
    #pragma unroll
    for (int o = 16; o; o >>= 1) {
        s += __shfl_xor_sync(0xffffffffu, s, o);
        q += __shfl_xor_sync(0xffffffffu, q, o);
    }
    float mean = s * (1.f / HD_);
    float var  = q * (1.f / HD_) - mean * mean;
    float rstd = rsqrtf(var + EPS_);
    float* dst = &outb[((size_t)bh * N_ + n) * HD_];
    #pragma unroll
    for (int p = 0; p < 3; p++) {
        int c = lane + 32 * p;
        dst[c] = (val[p] - mean) * rstd * gamma[c] + beta[c];
    }
}

// ---------------- K3: flash attention, full tf32 MMA, prefetch -------------
// grid (25, 8). 64 Q rows x 64-key chunks. GEMM1 = QK^T MMA. GEMM2 = P@V MMA
// reading B-fragments straight from row-major V at stride 104 (bank-bijective:
// 104%32=8 -> bank = 8t+g+const). K/V gmem loads software-prefetched into
// registers, issued before GEMM2 of the previous chunk. exp2-folded softmax.
__global__ void __launch_bounds__(256, 2) k_flash(const float* __restrict__ rph,
                                                  const float* __restrict__ rpw,
                                                  const float* __restrict__ rpt) {
    extern __shared__ float sm[];
    float*    Qs = sm;                       // [64][100] fp32
    unsigned* Ks = (unsigned*)(sm + 6400);   // [64][100] tf32, pre-scaled by KSC_
    unsigned* Vs = (unsigned*)(sm + 12800);  // [64][104] tf32 row-major
    unsigned* Ps = (unsigned*)(sm + 19456);  // [64][68]  tf32
    float*    Rh = sm + 23808;               // [64][14]  (x log2e)
    float*    Rw = sm + 24704;               // [64][14]
    float*    Rt = sm + 25600;               // [64][8]
    float*    Ls = sm + 26112;               // [64][2]
    // total 26240 floats = 104960 B

    int bh = blockIdx.y;
    int i0 = blockIdx.x * 64;
    int tid = threadIdx.x;
    int wid = tid >> 5, lane = tid & 31;
    int wm = wid >> 1, wn = wid & 1;
    int g = lane >> 2, t = lane & 3;
    const int ra = 16 * wm + g;
    const int rb = ra + 8;

    const float* Qg = g_q + ((size_t)bh * N_ + i0) * HD_;
    #pragma unroll
    for (int it = 0; it < 6; it++) {
        int idx = tid + 256 * it;
        int r = idx / 24, c4 = idx % 24;
        float4 qv = make_float4(0.f, 0.f, 0.f, 0.f);
        if (i0 + r < N_) qv = *(const float4*)&Qg[r * 96 + c4 * 4];
        *(float4*)&Qs[r * 100 + c4 * 4] = qv;
    }
    __syncthreads();

    // ---- rel-pos bias dots from Qs (scaled by log2e for exp2 softmax) ----
    #pragma unroll
    for (int idx = tid; idx < 2304; idx += 256) {
        int r = idx / 36, e = idx - (idx / 36) * 36;
        int i = i0 + r;
        const float* tab = rph;
        float* dst;
        bool valid = (i < N_);
        int it = i / 196;
        int rm = i - it * 196;
        int ih = rm / 14, iw = rm - ih * 14;
        if (e < 14)      { tab = rph + (ih - e + 13) * HD_;        dst = &Rh[r * 14 + e]; }
        else if (e < 28) { int k = e - 14; tab = rpw + (iw - k + 13) * HD_; dst = &Rw[r * 14 + k]; }
        else             { int k = e - 28; tab = rpt + (it - k + 7) * HD_;  dst = &Rt[r * 8 + k]; }
        float s = 0.f;
        if (valid) {
            #pragma unroll 6
            for (int c4 = 0; c4 < 24; c4++) {
                float4 a = *(float4*)&Qs[r * 100 + c4 * 4];
                float4 b = *(const float4*)&tab[c4 * 4];
                s += a.x * b.x + a.y * b.y + a.z * b.z + a.w * b.w;
            }
        }
        *dst = s * LOG2E_;
    }

    float lpA = 0.f, lpB = 0.f;
    float accO[6][4] = {};

    const float* Kg = g_k + (size_t)bh * N_ * HD_;
    const float* Vg = g_v + (size_t)bh * N_ * HD_;

    // staging-row constants per thread
    int srow[6], sc4[6];
    #pragma unroll
    for (int it = 0; it < 6; it++) {
        int idx = tid + 256 * it;
        srow[it] = idx / 24;
        sc4[it]  = idx % 24;
    }

    float4 kReg[6], vReg[6];
    // prefetch chunk 0
    #pragma unroll
    for (int it = 0; it < 6; it++) {
        int j = srow[it];
        if (j < N_) {
            kReg[it] = *(const float4*)&Kg[(size_t)j * 96 + sc4[it] * 4];
            vReg[it] = *(const float4*)&Vg[(size_t)j * 96 + sc4[it] * 4];
        } else {
            kReg[it] = make_float4(0.f, 0.f, 0.f, 0.f);
            vReg[it] = kReg[it];
        }
    }

    for (int ch = 0; ch < 25; ch++) {
        int j0 = ch * 64;
        __syncthreads();                     // Ks/Vs free (prev GEMM2 done)
        #pragma unroll
        for (int it = 0; it < 6; it++) {
            int row = srow[it], c4 = sc4[it];
            uint4 kt;
            kt.x = cvt_tf32(kReg[it].x * KSC_);
            kt.y = cvt_tf32(kReg[it].y * KSC_);
            kt.z = cvt_tf32(kReg[it].z * KSC_);
            kt.w = cvt_tf32(kReg[it].w * KSC_);
            *(uint4*)&Ks[row * 100 + c4 * 4] = kt;
            uint4 vt;
            vt.x = cvt_tf32(vReg[it].x);
            vt.y = cvt_tf32(vReg[it].y);
            vt.z = cvt_tf32(vReg[it].z);
            vt.w = cvt_tf32(vReg[it].w);
            *(uint4*)&Vs[row * 104 + c4 * 4] = vt;
        }
        __syncthreads();

        // ---- GEMM1: S = Q @ (K*ksc)^T via tf32 mma ----
        float c[4][4] = {};
        const unsigned* Qa = (const unsigned*)Qs;
        #pragma unroll
        for (int k0 = 0; k0 < 96; k0 += 8) {
            unsigned a0 = Qa[ra * 100 + k0 + t];
            unsigned a1 = Qa[rb * 100 + k0 + t];
            unsigned a2 = Qa[ra * 100 + k0 + t + 4];
            unsigned a3 = Qa[rb * 100 + k0 + t + 4];
            #pragma unroll
            for (int u = 0; u < 4; u++) {
                int kr = 32 * wn + 8 * u + g;
                unsigned b0 = Ks[kr * 100 + k0 + t];
                unsigned b1 = Ks[kr * 100 + k0 + t + 4];
                mma_tf32(c[u], a0, a1, a2, a3, b0, b1);
            }
        }

        // ---- bias + exp2 in C-fragment layout; P stored tf32 ----
        #pragma unroll
        for (int u = 0; u < 4; u++) {
            int cc = 32 * wn + 8 * u + 2 * t;
            #pragma unroll
            for (int q2 = 0; q2 < 2; q2++) {
                int j = j0 + cc + q2;
                unsigned pAb = 0, pBb = 0;
                if (j < N_) {
                    int jt = j / 196;
                    int jr = j - jt * 196;
                    int jh = jr / 14;
                    int jw = jr - jh * 14;
                    pAb = cvt_tf32(ex2f(c[u][q2]     + Rt[ra * 8 + jt] + Rh[ra * 14 + jh] + Rw[ra * 14 + jw]));
                    pBb = cvt_tf32(ex2f(c[u][q2 + 2] + Rt[rb * 8 + jt] + Rh[rb * 14 + jh] + Rw[rb * 14 + jw]));
                }
                lpA += __uint_as_float(pAb);
                lpB += __uint_as_float(pBb);
                Ps[ra * 68 + cc + q2] = pAb;
                Ps[rb * 68 + cc + q2] = pBb;
            }
        }

        // ---- prefetch next chunk (latency hides behind barrier + GEMM2) ----
        if (ch < 24) {
            int nj0 = j0 + 64;
            #pragma unroll
            for (int it = 0; it < 6; it++) {
                int j = nj0 + srow[it];
                if (j < N_) {
                    kReg[it] = *(const float4*)&Kg[(size_t)j * 96 + sc4[it] * 4];
                    vReg[it] = *(const float4*)&Vg[(size_t)j * 96 + sc4[it] * 4];
                } else {
                    kReg[it] = make_float4(0.f, 0.f, 0.f, 0.f);
                    vReg[it] = kReg[it];
                }
            }
        }
        __syncthreads();

        // ---- GEMM2: O += P @ V via tf32 mma (B read from row-major Vs) ----
        #pragma unroll
        for (int k0 = 0; k0 < 64; k0 += 8) {
            unsigned a0 = Ps[ra * 68 + k0 + t];
            unsigned a1 = Ps[rb * 68 + k0 + t];
            unsigned a2 = Ps[ra * 68 + k0 + t + 4];
            unsigned a3 = Ps[rb * 68 + k0 + t + 4];
            #pragma unroll
            for (int u = 0; u < 6; u++) {
                int nr = 48 * wn + 8 * u + g;
                unsigned b0 = Vs[(k0 + t) * 104 + nr];
                unsigned b1 = Vs[(k0 + t + 4) * 104 + nr];
                mma_tf32(accO[u], a0, a1, a2, a3, b0, b1);
            }
        }
    }

    // ---- row-sum combine ----
    lpA += __shfl_xor_sync(0xffffffffu, lpA, 1);
    lpA += __shfl_xor_sync(0xffffffffu, lpA, 2);
    lpB += __shfl_xor_sync(0xffffffffu, lpB, 1);
    lpB += __shfl_xor_sync(0xffffffffu, lpB, 2);
    if (t == 0) {
        Ls[ra * 2 + wn] = lpA;
        Ls[rb * 2 + wn] = lpB;
    }
    __syncthreads();

    // ---- epilogue (MMA C layout): O/l + residual q -> g_ctx ----
    int b = bh >> 2, nh = bh & 3;
    #pragma unroll
    for (int half = 0; half < 2; half++) {
        int r = ra + 8 * half;
        int i = i0 + r;
        if (i >= N_) continue;
        float inv = 1.f / (Ls[r * 2] + Ls[r * 2 + 1]);
        float* dst = &g_ctx[(((size_t)b * N_ + i) * NH_ + nh) * HD_];
        #pragma unroll
        for (int u = 0; u < 6; u++) {
            int cc = 48 * wn + 8 * u + 2 * t;
            float2 v;
            v.x = accO[u][2 * half]     * inv + Qs[r * 100 + cc];
            v.y = accO[u][2 * half + 1] * inv + Qs[r * 100 + cc + 1];
            *(float2*)&dst[cc] = v;
        }
    }
}

// ---------------- K4: output projection + bias (tf32 MMA) ------------------
__global__ void __launch_bounds__(256, 2) k_proj(const float* __restrict__ proj_w,
                                                 const float* __restrict__ proj_b,
                                                 float* __restrict__ out) {
    int n0 = blockIdx.x * 64, m0 = blockIdx.y * 64;
    int tid = threadIdx.x;
    int wid = tid >> 5, lane = tid & 31;
    int wm = wid >> 1, wn = wid & 1;
    int g = lane >> 2, t = lane & 3;
    float acc[4][4] = {};
    mma_nt64(g_ctx, proj_w, DIM_, m0, n0, wm, wn, g, t, tid, acc);

    int ra = 16 * wm + g;
    #pragma unroll
    for (int half = 0; half < 2; half++) {
        int m = m0 + ra + 8 * half;
        #pragma unroll
        for (int u = 0; u < 4; u++) {
            int o = n0 + 32 * wn + 8 * u + 2 * t;
            float2 v;
            v.x = acc[u][2 * half]     + proj_b[o];
            v.y = acc[u][2 * half + 1] + proj_b[o + 1];
            *(float2*)&out[(size_t)m * DIM_ + o] = v;
        }
    }
}

// ---------------- launch ----------------------------------------------------
extern "C" void kernel_launch(void* const* d_in, const int* in_sizes, int n_in,
                              void* d_out, int out_size) {
    const float* x      = (const float*)d_in[0];
    const float* qkv_w  = (const float*)d_in[1];
    const float* proj_w = (const float*)d_in[2];
    const float* proj_b = (const float*)d_in[3];
    const float* pqw    = (const float*)d_in[4];
    const float* pkw    = (const float*)d_in[5];
    const float* pvw    = (const float*)d_in[6];
    const float* nqw    = (const float*)d_in[7];
    const float* nqb    = (const float*)d_in[8];
    const float* nkw    = (const float*)d_in[9];
    const float* nkb    = (const float*)d_in[10];
    const float* nvw    = (const float*)d_in[11];
    const float* nvb    = (const float*)d_in[12];
    const float* rph    = (const float*)d_in[13];
    const float* rpw    = (const float*)d_in[14];
    const float* rpt    = (const float*)d_in[15];
    float* out = (float*)d_out;

    cudaFuncSetAttribute(k_flash, cudaFuncAttributeMaxDynamicSharedMemorySize, 104960);

    k_qkv<<<dim3(18, 49), 256>>>(x, qkv_w);
    k_conv_ln<<<(BH_ * N_ * 3) / 4, 128>>>(pqw, pkw, pvw, nqw, nqb, nkw, nkb, nvw, nvb);
    k_flash<<<dim3(25, BH_), 256, 104960>>>(rph, rpw, rpt);
    k_proj<<<dim3(6, 49), 256>>>(proj_w, proj_b, out);
}

// round 13
// speedup vs baseline: 1.1843x; 1.1843x over previous
#include <cuda_runtime.h>
#include <cuda_bf16.h>
#include <math.h>

#define B_    2
#define NH_   4
#define T_    8
#define H_    14
#define W_    14
#define N_    1568
#define DIM_  384
#define HD_   96
#define BH_   (B_*NH_)
#define M_    (B_*N_)
#define EPS_  1e-6f
#define SCALE_ 0.1020620726159657f     // 96^-0.5
#define LOG2E_ 1.4426950408889634f
#define KSC_   0.1472444463f           // SCALE_ * LOG2E_

typedef unsigned long long ull;

__device__ __forceinline__ unsigned cvt_tf32(float f) {
    unsigned r;
    asm("cvt.rna.tf32.f32 %0, %1;" : "=r"(r) : "f"(f));
    return r;
}
__device__ __forceinline__ float ex2f(float x) {
    float r;
    asm("ex2.approx.ftz.f32 %0, %1;" : "=f"(r) : "f"(x));
    return r;
}
// tf32 mma m16n8k8: D += A*B, A row-major 16x8, B "col" ([n][k]) 8x8
__device__ __forceinline__ void mma_tf32(float c[4], unsigned a0, unsigned a1,
                                         unsigned a2, unsigned a3,
                                         unsigned b0, unsigned b1) {
    asm("mma.sync.aligned.m16n8k8.row.col.f32.tf32.tf32.f32 "
        "{%0,%1,%2,%3}, {%4,%5,%6,%7}, {%8,%9}, {%0,%1,%2,%3};"
        : "+f"(c[0]), "+f"(c[1]), "+f"(c[2]), "+f"(c[3])
        : "r"(a0), "r"(a1), "r"(a2), "r"(a3), "r"(b0), "r"(b1));
}

// ---------------- scratch ---------------------------------------------------
__device__ float g_q_raw[BH_ * N_ * HD_];
__device__ float g_k_raw[BH_ * N_ * HD_];
__device__ float g_v_raw[BH_ * N_ * HD_];
__device__ float g_q[BH_ * N_ * HD_];
__device__ float g_k[BH_ * N_ * HD_];
__device__ float g_v[BH_ * N_ * HD_];
__device__ float g_ctx[B_ * N_ * DIM_];

// ------- 64x64 NT GEMM core, tf32 MMA, double-buffered smem ----------------
__device__ __forceinline__ void mma_nt64(const float* __restrict__ A,
                                         const float* __restrict__ Bw,
                                         int K, int m0, int n0,
                                         int wm, int wn, int g, int t,
                                         int tid, float acc[4][4]) {
    __shared__ unsigned Xs[2][64 * 36];
    __shared__ unsigned Ws[2][64 * 36];
    const int r0 = tid >> 3, c40 = tid & 7;
    const int r1 = (tid + 256) >> 3, c41 = tid & 7;
    const int ra = 16 * wm + g;

    float4 pa0 = *(const float4*)&A[(size_t)(m0 + r0) * K + c40 * 4];
    float4 pb0 = *(const float4*)&Bw[(size_t)(n0 + r0) * K + c40 * 4];
    float4 pa1 = *(const float4*)&A[(size_t)(m0 + r1) * K + c41 * 4];
    float4 pb1 = *(const float4*)&Bw[(size_t)(n0 + r1) * K + c41 * 4];
    #define ST_TF32(dst, v) do { uint4 _u; _u.x = cvt_tf32((v).x); _u.y = cvt_tf32((v).y); \
        _u.z = cvt_tf32((v).z); _u.w = cvt_tf32((v).w); *(uint4*)(dst) = _u; } while (0)
    ST_TF32(&Xs[0][r0 * 36 + c40 * 4], pa0);
    ST_TF32(&Ws[0][r0 * 36 + c40 * 4], pb0);
    ST_TF32(&Xs[0][r1 * 36 + c41 * 4], pa1);
    ST_TF32(&Ws[0][r1 * 36 + c41 * 4], pb1);
    __syncthreads();

    int p = 0;
    for (int k0 = 0; k0 < K; k0 += 32) {
        if (k0 + 32 < K) {
            pa0 = *(const float4*)&A[(size_t)(m0 + r0) * K + k0 + 32 + c40 * 4];
            pb0 = *(const float4*)&Bw[(size_t)(n0 + r0) * K + k0 + 32 + c40 * 4];
            pa1 = *(const float4*)&A[(size_t)(m0 + r1) * K + k0 + 32 + c41 * 4];
            pb1 = *(const float4*)&Bw[(size_t)(n0 + r1) * K + k0 + 32 + c41 * 4];
        }
        #pragma unroll
        for (int ks = 0; ks < 4; ks++) {
            int kk = ks * 8;
            unsigned a0 = Xs[p][ra * 36 + kk + t];
            unsigned a1 = Xs[p][(ra + 8) * 36 + kk + t];
            unsigned a2 = Xs[p][ra * 36 + kk + t + 4];
            unsigned a3 = Xs[p][(ra + 8) * 36 + kk + t + 4];
            #pragma unroll
            for (int u = 0; u < 4; u++) {
                int nr = 32 * wn + 8 * u + g;
                unsigned b0 = Ws[p][nr * 36 + kk + t];
                unsigned b1 = Ws[p][nr * 36 + kk + t + 4];
                mma_tf32(acc[u], a0, a1, a2, a3, b0, b1);
            }
        }
        if (k0 + 32 < K) {
            ST_TF32(&Xs[1 - p][r0 * 36 + c40 * 4], pa0);
            ST_TF32(&Ws[1 - p][r0 * 36 + c40 * 4], pb0);
            ST_TF32(&Xs[1 - p][r1 * 36 + c41 * 4], pa1);
            ST_TF32(&Ws[1 - p][r1 * 36 + c41 * 4], pb1);
            __syncthreads();
            p ^= 1;
        }
    }
    #undef ST_TF32
}

// ---------------- K1: QKV projection (tf32 MMA) -----------------------------
__global__ void __launch_bounds__(256, 2) k_qkv(const float* __restrict__ x,
                                                const float* __restrict__ qkv_w) {
    int n0 = blockIdx.x * 64, m0 = blockIdx.y * 64;
    int tid = threadIdx.x;
    int wid = tid >> 5, lane = tid & 31;
    int wm = wid >> 1, wn = wid & 1;
    int g = lane >> 2, t = lane & 3;
    float acc[4][4] = {};
    mma_nt64(x, qkv_w, DIM_, m0, n0, wm, wn, g, t, tid, acc);

    int ra = 16 * wm + g;
    #pragma unroll
    for (int half = 0; half < 2; half++) {
        int m = m0 + ra + 8 * half;
        int b = m / N_, n = m - b * N_;
        #pragma unroll
        for (int u = 0; u < 4; u++) {
            int o = n0 + 32 * wn + 8 * u + 2 * t;
            int s = o / DIM_;
            int rem = o - s * DIM_;
            int head = rem / HD_;
            int c = rem - head * HD_;
            float* dst = (s == 0) ? g_q_raw : (s == 1) ? g_k_raw : g_v_raw;
            float2 v = make_float2(acc[u][2 * half], acc[u][2 * half + 1]);
            *(float2*)&dst[((size_t)(b * NH_ + head) * N_ + n) * HD_ + c] = v;
        }
    }
}

// ---------------- K2: conv3x3x3 + LayerNorm, warp per token ---------------
__global__ void __launch_bounds__(128) k_conv_ln(
        const float* __restrict__ wq, const float* __restrict__ wk,
        const float* __restrict__ wv,
        const float* __restrict__ gq, const float* __restrict__ bq,
        const float* __restrict__ gk, const float* __restrict__ bk,
        const float* __restrict__ gv, const float* __restrict__ bv) {
    int gid = blockIdx.x * 4 + (threadIdx.x >> 5);
    int lane = threadIdx.x & 31;
    int z = gid / (BH_ * N_);
    int rem0 = gid - z * (BH_ * N_);
    int bh = rem0 / N_;
    int n = rem0 - bh * N_;
    const float* inb  = (z == 0) ? g_q_raw : (z == 1) ? g_k_raw : g_v_raw;
    float*       outb = (z == 0) ? g_q     : (z == 1) ? g_k     : g_v;
    const float* wt    = (z == 0) ? wq : (z == 1) ? wk : wv;
    const float* gamma = (z == 0) ? gq : (z == 1) ? gk : gv;
    const float* beta  = (z == 0) ? bq : (z == 1) ? bk : bv;

    int tt = n / (H_ * W_);
    int rem = n - tt * (H_ * W_);
    int hh = rem / W_, ww = rem - (rem / W_) * W_;

    float val[3] = {0.f, 0.f, 0.f};
    #pragma unroll
    for (int dt = -1; dt <= 1; dt++) {
        int t2 = tt + dt;
        if (t2 < 0 || t2 >= T_) continue;
        #pragma unroll
        for (int dh = -1; dh <= 1; dh++) {
            int h2 = hh + dh;
            if (h2 < 0 || h2 >= H_) continue;
            #pragma unroll
            for (int dw = -1; dw <= 1; dw++) {
                int w2 = ww + dw;
                if (w2 < 0 || w2 >= W_) continue;
                int n2 = (t2 * H_ + h2) * W_ + w2;
                const float* src = &inb[((size_t)bh * N_ + n2) * HD_];
                int tap = (dt + 1) * 9 + (dh + 1) * 3 + (dw + 1);
                #pragma unroll
                for (int p = 0; p < 3; p++) {
                    int c = lane + 32 * p;
                    val[p] += wt[c * 27 + tap] * src[c];
                }
            }
        }
    }
    float s = val[0] + val[1] + val[2];
    float q = val[0]*val[0] + val[1]*val[1] + val[2]*val[2];
    #pragma unroll
    for (int o = 16; o; o >>= 1) {
        s += __shfl_xor_sync(0xffffffffu, s, o);
        q += __shfl_xor_sync(0xffffffffu, q, o);
    }
    float mean = s * (1.f / HD_);
    float var  = q * (1.f / HD_) - mean * mean;
    float rstd = rsqrtf(var + EPS_);
    float* dst = &outb[((size_t)bh * N_ + n) * HD_];
    #pragma unroll
    for (int p = 0; p < 3; p++) {
        int c = lane + 32 * p;
        dst[c] = (val[p] - mean) * rstd * gamma[c] + beta[c];
    }
}

// ---------------- K3: flash attention, 32 rows x 56-key chunks -------------
// grid (49, 8), 128 threads, 3 CTAs/SM (single full wave: 392/444 slots).
// 56*28 = 1568 and 32*49 = 1568 exactly -> no boundary guards anywhere.
// Q fragments hoisted to registers (tf32, pre-scaled by SCALE*log2e).
// 4 warps as 2m x 2n; wn0 covers keys 0-31 (4 n-tiles), wn1 keys 32-55 (3).
__global__ void __launch_bounds__(128, 3) k_flash(const float* __restrict__ rph,
                                                  const float* __restrict__ rpw,
                                                  const float* __restrict__ rpt) {
    extern __shared__ float sm[];
    float*    Qs = sm;                        // [32][96]  fp32 (exact, residual)
    unsigned* Ks = (unsigned*)(sm + 3072);    // [56][100] tf32
    unsigned* Vs = (unsigned*)(sm + 8672);    // [56][104] tf32
    unsigned* Ps = (unsigned*)(sm + 14496);   // [32][68]  tf32
    float*    Rh = sm + 16672;                // [32][14]  (x log2e)
    float*    Rw = sm + 17120;                // [32][14]
    float*    Rt = sm + 17568;                // [32][8]
    float*    Ls = sm + 17824;                // [32][2]
    // total 17888 floats = 71552 B

    int bh = blockIdx.y;
    int i0 = blockIdx.x * 32;
    int tid = threadIdx.x;
    int wid = tid >> 5, lane = tid & 31;
    int wm = wid >> 1, wn = wid & 1;
    int g = lane >> 2, t = lane & 3;
    const int ra = 16 * wm + g;
    const int rb = ra + 8;
    const int NU1 = wn ? 3 : 4;              // GEMM1 n-tiles for this warp

    // ---- load Q tile (768 float4) ----
    const float* Qg = g_q + ((size_t)bh * N_ + i0) * HD_;
    #pragma unroll
    for (int it = 0; it < 6; it++) {
        int idx = tid + 128 * it;
        int r = idx / 24, c4 = idx % 24;
        *(float4*)&Qs[r * 96 + c4 * 4] = *(const float4*)&Qg[r * 96 + c4 * 4];
    }
    __syncthreads();

    // ---- hoist Q fragments to registers (tf32, pre-scaled by KSC_) ----
    unsigned qf[12][4];
    #pragma unroll
    for (int ks = 0; ks < 12; ks++) {
        int k0 = ks * 8;
        qf[ks][0] = cvt_tf32(Qs[ra * 96 + k0 + t] * KSC_);
        qf[ks][1] = cvt_tf32(Qs[rb * 96 + k0 + t] * KSC_);
        qf[ks][2] = cvt_tf32(Qs[ra * 96 + k0 + t + 4] * KSC_);
        qf[ks][3] = cvt_tf32(Qs[rb * 96 + k0 + t + 4] * KSC_);
    }

    // ---- rel-pos bias dots from Qs (x log2e) ----
    #pragma unroll
    for (int idx = tid; idx < 1152; idx += 128) {
        int r = idx / 36, e = idx - (idx / 36) * 36;
        int i = i0 + r;
        int it = i / 196;
        int rm = i - it * 196;
        int ih = rm / 14, iw = rm - ih * 14;
        const float* tab;
        float* dst;
        if (e < 14)      { tab = rph + (ih - e + 13) * HD_;        dst = &Rh[r * 14 + e]; }
        else if (e < 28) { int k = e - 14; tab = rpw + (iw - k + 13) * HD_; dst = &Rw[r * 14 + k]; }
        else             { int k = e - 28; tab = rpt + (it - k + 7) * HD_;  dst = &Rt[r * 8 + k]; }
        float s = 0.f;
        #pragma unroll 6
        for (int c4 = 0; c4 < 24; c4++) {
            float4 a = *(float4*)&Qs[r * 96 + c4 * 4];
            float4 b = *(const float4*)&tab[c4 * 4];
            s += a.x * b.x + a.y * b.y + a.z * b.z + a.w * b.w;
        }
        *dst = s * LOG2E_;
    }

    float lpA = 0.f, lpB = 0.f;
    float accO[6][4] = {};

    const float* Kg = g_k + (size_t)bh * N_ * HD_;
    const float* Vg = g_v + (size_t)bh * N_ * HD_;

    for (int ch = 0; ch < 28; ch++) {
        int j0 = ch * 56;
        __syncthreads();
        // ---- staging: 56 rows x 24 float4 = 1344 items, no guards ----
        #pragma unroll
        for (int it = 0; it < 11; it++) {
            int idx = tid + 128 * it;
            if (it == 10 && tid >= 64) break;
            int row = idx / 24, c4 = idx % 24;
            int j = j0 + row;
            float4 kv = *(const float4*)&Kg[(size_t)j * 96 + c4 * 4];
            float4 vv = *(const float4*)&Vg[(size_t)j * 96 + c4 * 4];
            uint4 kt;
            kt.x = cvt_tf32(kv.x); kt.y = cvt_tf32(kv.y);
            kt.z = cvt_tf32(kv.z); kt.w = cvt_tf32(kv.w);
            *(uint4*)&Ks[row * 100 + c4 * 4] = kt;
            uint4 vt;
            vt.x = cvt_tf32(vv.x); vt.y = cvt_tf32(vv.y);
            vt.z = cvt_tf32(vv.z); vt.w = cvt_tf32(vv.w);
            *(uint4*)&Vs[row * 104 + c4 * 4] = vt;
        }
        __syncthreads();

        // ---- GEMM1: S = (Q*ksc) @ K^T, A-frags in registers ----
        float c[4][4] = {};
        #pragma unroll
        for (int ks = 0; ks < 12; ks++) {
            int k0 = ks * 8;
            #pragma unroll
            for (int u = 0; u < 4; u++) {
                if (u >= NU1) break;
                int kr = 32 * wn + 8 * u + g;
                unsigned b0 = Ks[kr * 100 + k0 + t];
                unsigned b1 = Ks[kr * 100 + k0 + t + 4];
                mma_tf32(c[u], qf[ks][0], qf[ks][1], qf[ks][2], qf[ks][3], b0, b1);
            }
        }

        // ---- bias + exp2; P stored tf32 (uint2) ----
        #pragma unroll
        for (int u = 0; u < 4; u++) {
            if (u >= NU1) break;
            int cc = 32 * wn + 8 * u + 2 * t;
            int j = j0 + cc;
            int jt0 = j / 196;         int jr0 = j - jt0 * 196;
            int jh0 = jr0 / 14;        int jw0 = jr0 - jh0 * 14;
            int j1 = j + 1;
            int jt1 = j1 / 196;        int jr1 = j1 - jt1 * 196;
            int jh1 = jr1 / 14;        int jw1 = jr1 - jh1 * 14;
            float pA0 = ex2f(c[u][0] + Rt[ra * 8 + jt0] + Rh[ra * 14 + jh0] + Rw[ra * 14 + jw0]);
            float pA1 = ex2f(c[u][1] + Rt[ra * 8 + jt1] + Rh[ra * 14 + jh1] + Rw[ra * 14 + jw1]);
            float pB0 = ex2f(c[u][2] + Rt[rb * 8 + jt0] + Rh[rb * 14 + jh0] + Rw[rb * 14 + jw0]);
            float pB1 = ex2f(c[u][3] + Rt[rb * 8 + jt1] + Rh[rb * 14 + jh1] + Rw[rb * 14 + jw1]);
            unsigned a0 = cvt_tf32(pA0), a1 = cvt_tf32(pA1);
            unsigned b0 = cvt_tf32(pB0), b1 = cvt_tf32(pB1);
            lpA += __uint_as_float(a0) + __uint_as_float(a1);
            lpB += __uint_as_float(b0) + __uint_as_float(b1);
            *(uint2*)&Ps[ra * 68 + cc] = make_uint2(a0, a1);
            *(uint2*)&Ps[rb * 68 + cc] = make_uint2(b0, b1);
        }
        __syncthreads();

        // ---- GEMM2: O += P @ V (B read from row-major Vs, stride 104) ----
        #pragma unroll
        for (int ks = 0; ks < 7; ks++) {
            int k0 = ks * 8;
            unsigned a0 = Ps[ra * 68 + k0 + t];
            unsigned a1 = Ps[rb * 68 + k0 + t];
            unsigned a2 = Ps[ra * 68 + k0 + t + 4];
            unsigned a3 = Ps[rb * 68 + k0 + t + 4];
            #pragma unroll
            for (int u = 0; u < 6; u++) {
                int nr = 48 * wn + 8 * u + g;
                unsigned b0 = Vs[(k0 + t) * 104 + nr];
                unsigned b1 = Vs[(k0 + t + 4) * 104 + nr];
                mma_tf32(accO[u], a0, a1, a2, a3, b0, b1);
            }
        }
    }

    // ---- row-sum combine ----
    lpA += __shfl_xor_sync(0xffffffffu, lpA, 1);
    lpA += __shfl_xor_sync(0xffffffffu, lpA, 2);
    lpB += __shfl_xor_sync(0xffffffffu, lpB, 1);
    lpB += __shfl_xor_sync(0xffffffffu, lpB, 2);
    if (t == 0) {
        Ls[ra * 2 + wn] = lpA;
        Ls[rb * 2 + wn] = lpB;
    }
    __syncthreads();

    // ---- epilogue (MMA C layout): O/l + residual q -> g_ctx ----
    int b = bh >> 2, nh = bh & 3;
    #pragma unroll
    for (int half = 0; half < 2; half++) {
        int r = ra + 8 * half;
        int i = i0 + r;
        float inv = 1.f / (Ls[r * 2] + Ls[r * 2 + 1]);
        float* dst = &g_ctx[(((size_t)b * N_ + i) * NH_ + nh) * HD_];
        #pragma unroll
        for (int u = 0; u < 6; u++) {
            int cc = 48 * wn + 8 * u + 2 * t;
            float2 v;
            v.x = accO[u][2 * half]     * inv + Qs[r * 96 + cc];
            v.y = accO[u][2 * half + 1] * inv + Qs[r * 96 + cc + 1];
            *(float2*)&dst[cc] = v;
        }
    }
}

// ---------------- K4: output projection + bias (tf32 MMA) ------------------
__global__ void __launch_bounds__(256, 2) k_proj(const float* __restrict__ proj_w,
                                                 const float* __restrict__ proj_b,
                                                 float* __restrict__ out) {
    int n0 = blockIdx.x * 64, m0 = blockIdx.y * 64;
    int tid = threadIdx.x;
    int wid = tid >> 5, lane = tid & 31;
    int wm = wid >> 1, wn = wid & 1;
    int g = lane >> 2, t = lane & 3;
    float acc[4][4] = {};
    mma_nt64(g_ctx, proj_w, DIM_, m0, n0, wm, wn, g, t, tid, acc);

    int ra = 16 * wm + g;
    #pragma unroll
    for (int half = 0; half < 2; half++) {
        int m = m0 + ra + 8 * half;
        #pragma unroll
        for (int u = 0; u < 4; u++) {
            int o = n0 + 32 * wn + 8 * u + 2 * t;
            float2 v;
            v.x = acc[u][2 * half]     + proj_b[o];
            v.y = acc[u][2 * half + 1] + proj_b[o + 1];
            *(float2*)&out[(size_t)m * DIM_ + o] = v;
        }
    }
}

// ---------------- launch ----------------------------------------------------
extern "C" void kernel_launch(void* const* d_in, const int* in_sizes, int n_in,
                              void* d_out, int out_size) {
    const float* x      = (const float*)d_in[0];
    const float* qkv_w  = (const float*)d_in[1];
    const float* proj_w = (const float*)d_in[2];
    const float* proj_b = (const float*)d_in[3];
    const float* pqw    = (const float*)d_in[4];
    const float* pkw    = (const float*)d_in[5];
    const float* pvw    = (const float*)d_in[6];
    const float* nqw    = (const float*)d_in[7];
    const float* nqb    = (const float*)d_in[8];
    const float* nkw    = (const float*)d_in[9];
    const float* nkb    = (const float*)d_in[10];
    const float* nvw    = (const float*)d_in[11];
    const float* nvb    = (const float*)d_in[12];
    const float* rph    = (const float*)d_in[13];
    const float* rpw    = (const float*)d_in[14];
    const float* rpt    = (const float*)d_in[15];
    float* out = (float*)d_out;

    cudaFuncSetAttribute(k_flash, cudaFuncAttributeMaxDynamicSharedMemorySize, 71552);

    k_qkv<<<dim3(18, 49), 256>>>(x, qkv_w);
    k_conv_ln<<<(BH_ * N_ * 3) / 4, 128>>>(pqw, pkw, pvw, nqw, nqb, nkw, nkb, nvw, nvb);
    k_flash<<<dim3(49, BH_), 128, 71552>>>(rph, rpw, rpt);
    k_proj<<<dim3(6, 49), 256>>>(proj_w, proj_b, out);
}

// round 15
// speedup vs baseline: 1.2683x; 1.0709x over previous
#include <cuda_runtime.h>
#include <cuda_bf16.h>
#include <math.h>

#define B_    2
#define NH_   4
#define T_    8
#define H_    14
#define W_    14
#define N_    1568
#define DIM_  384
#define HD_   96
#define BH_   (B_*NH_)
#define M_    (B_*N_)
#define EPS_  1e-6f
#define SCALE_ 0.1020620726159657f     // 96^-0.5
#define LOG2E_ 1.4426950408889634f
#define KSC_   0.1472444463f           // SCALE_ * LOG2E_

typedef unsigned long long ull;

__device__ __forceinline__ unsigned cvt_tf32(float f) {
    unsigned r;
    asm("cvt.rna.tf32.f32 %0, %1;" : "=r"(r) : "f"(f));
    return r;
}
__device__ __forceinline__ float ex2f(float x) {
    float r;
    asm("ex2.approx.ftz.f32 %0, %1;" : "=f"(r) : "f"(x));
    return r;
}
__device__ __forceinline__ void cp_async16(unsigned smem_addr, const void* gptr) {
    asm volatile("cp.async.cg.shared.global [%0], [%1], 16;"
                 :: "r"(smem_addr), "l"(gptr));
}
// tf32 mma m16n8k8: D += A*B, A row-major 16x8, B "col" ([n][k]) 8x8
__device__ __forceinline__ void mma_tf32(float c[4], unsigned a0, unsigned a1,
                                         unsigned a2, unsigned a3,
                                         unsigned b0, unsigned b1) {
    asm("mma.sync.aligned.m16n8k8.row.col.f32.tf32.tf32.f32 "
        "{%0,%1,%2,%3}, {%4,%5,%6,%7}, {%8,%9}, {%0,%1,%2,%3};"
        : "+f"(c[0]), "+f"(c[1]), "+f"(c[2]), "+f"(c[3])
        : "r"(a0), "r"(a1), "r"(a2), "r"(a3), "r"(b0), "r"(b1));
}

// ---------------- scratch ---------------------------------------------------
__device__ float g_q_raw[BH_ * N_ * HD_];
__device__ float g_k_raw[BH_ * N_ * HD_];
__device__ float g_v_raw[BH_ * N_ * HD_];
__device__ float g_q[BH_ * N_ * HD_];
__device__ float g_k[BH_ * N_ * HD_];   // tf32-rounded bits (written by conv_ln)
__device__ float g_v[BH_ * N_ * HD_];   // tf32-rounded bits
__device__ float g_ctx[B_ * N_ * DIM_];

// ------- 64x64 NT GEMM core, tf32 MMA, double-buffered smem ----------------
__device__ __forceinline__ void mma_nt64(const float* __restrict__ A,
                                         const float* __restrict__ Bw,
                                         int K, int m0, int n0,
                                         int wm, int wn, int g, int t,
                                         int tid, float acc[4][4]) {
    __shared__ unsigned Xs[2][64 * 36];
    __shared__ unsigned Ws[2][64 * 36];
    const int r0 = tid >> 3, c40 = tid & 7;
    const int r1 = (tid + 256) >> 3, c41 = tid & 7;
    const int ra = 16 * wm + g;

    float4 pa0 = *(const float4*)&A[(size_t)(m0 + r0) * K + c40 * 4];
    float4 pb0 = *(const float4*)&Bw[(size_t)(n0 + r0) * K + c40 * 4];
    float4 pa1 = *(const float4*)&A[(size_t)(m0 + r1) * K + c41 * 4];
    float4 pb1 = *(const float4*)&Bw[(size_t)(n0 + r1) * K + c41 * 4];
    #define ST_TF32(dst, v) do { uint4 _u; _u.x = cvt_tf32((v).x); _u.y = cvt_tf32((v).y); \
        _u.z = cvt_tf32((v).z); _u.w = cvt_tf32((v).w); *(uint4*)(dst) = _u; } while (0)
    ST_TF32(&Xs[0][r0 * 36 + c40 * 4], pa0);
    ST_TF32(&Ws[0][r0 * 36 + c40 * 4], pb0);
    ST_TF32(&Xs[0][r1 * 36 + c41 * 4], pa1);
    ST_TF32(&Ws[0][r1 * 36 + c41 * 4], pb1);
    __syncthreads();

    int p = 0;
    for (int k0 = 0; k0 < K; k0 += 32) {
        if (k0 + 32 < K) {
            pa0 = *(const float4*)&A[(size_t)(m0 + r0) * K + k0 + 32 + c40 * 4];
            pb0 = *(const float4*)&Bw[(size_t)(n0 + r0) * K + k0 + 32 + c40 * 4];
            pa1 = *(const float4*)&A[(size_t)(m0 + r1) * K + k0 + 32 + c41 * 4];
            pb1 = *(const float4*)&Bw[(size_t)(n0 + r1) * K + k0 + 32 + c41 * 4];
        }
        #pragma unroll
        for (int ks = 0; ks < 4; ks++) {
            int kk = ks * 8;
            unsigned a0 = Xs[p][ra * 36 + kk + t];
            unsigned a1 = Xs[p][(ra + 8) * 36 + kk + t];
            unsigned a2 = Xs[p][ra * 36 + kk + t + 4];
            unsigned a3 = Xs[p][(ra + 8) * 36 + kk + t + 4];
            #pragma unroll
            for (int u = 0; u < 4; u++) {
                int nr = 32 * wn + 8 * u + g;
                unsigned b0 = Ws[p][nr * 36 + kk + t];
                unsigned b1 = Ws[p][nr * 36 + kk + t + 4];
                mma_tf32(acc[u], a0, a1, a2, a3, b0, b1);
            }
        }
        if (k0 + 32 < K) {
            ST_TF32(&Xs[1 - p][r0 * 36 + c40 * 4], pa0);
            ST_TF32(&Ws[1 - p][r0 * 36 + c40 * 4], pb0);
            ST_TF32(&Xs[1 - p][r1 * 36 + c41 * 4], pa1);
            ST_TF32(&Ws[1 - p][r1 * 36 + c41 * 4], pb1);
            __syncthreads();
            p ^= 1;
        }
    }
    #undef ST_TF32
}

// ---------------- K1: QKV projection (tf32 MMA) -----------------------------
__global__ void __launch_bounds__(256, 2) k_qkv(const float* __restrict__ x,
                                                const float* __restrict__ qkv_w) {
    int n0 = blockIdx.x * 64, m0 = blockIdx.y * 64;
    int tid = threadIdx.x;
    int wid = tid >> 5, lane = tid & 31;
    int wm = wid >> 1, wn = wid & 1;
    int g = lane >> 2, t = lane & 3;
    float acc[4][4] = {};
    mma_nt64(x, qkv_w, DIM_, m0, n0, wm, wn, g, t, tid, acc);

    int ra = 16 * wm + g;
    #pragma unroll
    for (int half = 0; half < 2; half++) {
        int m = m0 + ra + 8 * half;
        int b = m / N_, n = m - b * N_;
        #pragma unroll
        for (int u = 0; u < 4; u++) {
            int o = n0 + 32 * wn + 8 * u + 2 * t;
            int s = o / DIM_;
            int rem = o - s * DIM_;
            int head = rem / HD_;
            int c = rem - head * HD_;
            float* dst = (s == 0) ? g_q_raw : (s == 1) ? g_k_raw : g_v_raw;
            float2 v = make_float2(acc[u][2 * half], acc[u][2 * half + 1]);
            *(float2*)&dst[((size_t)(b * NH_ + head) * N_ + n) * HD_ + c] = v;
        }
    }
}

// ---------------- K2: conv3x3x3 + LayerNorm, warp per token ---------------
// K/V outputs are written tf32-rna-rounded so k_flash can stage them with
// cp.async and feed the MMA without any per-chunk cvt (same math as before;
// the rounding just moved to the producer).
__global__ void __launch_bounds__(128) k_conv_ln(
        const float* __restrict__ wq, const float* __restrict__ wk,
        const float* __restrict__ wv,
        const float* __restrict__ gq, const float* __restrict__ bq,
        const float* __restrict__ gk, const float* __restrict__ bk,
        const float* __restrict__ gv, const float* __restrict__ bv) {
    int gid = blockIdx.x * 4 + (threadIdx.x >> 5);
    int lane = threadIdx.x & 31;
    int z = gid / (BH_ * N_);
    int rem0 = gid - z * (BH_ * N_);
    int bh = rem0 / N_;
    int n = rem0 - bh * N_;
    const float* inb  = (z == 0) ? g_q_raw : (z == 1) ? g_k_raw : g_v_raw;
    float*       outb = (z == 0) ? g_q     : (z == 1) ? g_k     : g_v;
    const float* wt    = (z == 0) ? wq : (z == 1) ? wk : wv;
    const float* gamma = (z == 0) ? gq : (z == 1) ? gk : gv;
    const float* beta  = (z == 0) ? bq : (z == 1) ? bk : bv;

    int tt = n / (H_ * W_);
    int rem = n - tt * (H_ * W_);
    int hh = rem / W_, ww = rem - (rem / W_) * W_;

    float val[3] = {0.f, 0.f, 0.f};
    #pragma unroll
    for (int dt = -1; dt <= 1; dt++) {
        int t2 = tt + dt;
        if (t2 < 0 || t2 >= T_) continue;
        #pragma unroll
        for (int dh = -1; dh <= 1; dh++) {
            int h2 = hh + dh;
            if (h2 < 0 || h2 >= H_) continue;
            #pragma unroll
            for (int dw = -1; dw <= 1; dw++) {
                int w2 = ww + dw;
                if (w2 < 0 || w2 >= W_) continue;
                int n2 = (t2 * H_ + h2) * W_ + w2;
                const float* src = &inb[((size_t)bh * N_ + n2) * HD_];
                int tap = (dt + 1) * 9 + (dh + 1) * 3 + (dw + 1);
                #pragma unroll
                for (int p = 0; p < 3; p++) {
                    int c = lane + 32 * p;
                    val[p] += wt[c * 27 + tap] * src[c];
                }
            }
        }
    }
    float s = val[0] + val[1] + val[2];
    float q = val[0]*val[0] + val[1]*val[1] + val[2]*val[2];
    #pragma unroll
    for (int o = 16; o; o >>= 1) {
        s += __shfl_xor_sync(0xffffffffu, s, o);
        q += __shfl_xor_sync(0xffffffffu, q, o);
    }
    float mean = s * (1.f / HD_);
    float var  = q * (1.f / HD_) - mean * mean;
    float rstd = rsqrtf(var + EPS_);
    float* dst = &outb[((size_t)bh * N_ + n) * HD_];
    #pragma unroll
    for (int p = 0; p < 3; p++) {
        int c = lane + 32 * p;
        float outv = (val[p] - mean) * rstd * gamma[c] + beta[c];
        if (z != 0) outv = __uint_as_float(cvt_tf32(outv));   // pre-round K/V
        dst[c] = outv;
    }
}

// ---------------- K3: flash attention, cp.async staging --------------------
// grid (49, 8), 128 threads, 3 CTAs/SM. 32 Q rows x 56-key chunks, exact fit.
// K/V arrive in gmem already tf32-rounded -> staging is pure cp.async 16B
// copies (no cvt, no registers, no STS). Q frags hoisted (pre-scaled KSC_).
__global__ void __launch_bounds__(128, 3) k_flash(const float* __restrict__ rph,
                                                  const float* __restrict__ rpw,
                                                  const float* __restrict__ rpt) {
    extern __shared__ float sm[];
    float*    Qs = sm;                        // [32][96]  fp32 (exact, residual)
    unsigned* Ks = (unsigned*)(sm + 3072);    // [56][100] tf32 bits
    unsigned* Vs = (unsigned*)(sm + 8672);    // [56][104] tf32 bits
    unsigned* Ps = (unsigned*)(sm + 14496);   // [32][68]  tf32
    float*    Rh = sm + 16672;                // [32][14]  (x log2e)
    float*    Rw = sm + 17120;                // [32][14]
    float*    Rt = sm + 17568;                // [32][8]
    float*    Ls = sm + 17824;                // [32][2]
    // total 17888 floats = 71552 B

    int bh = blockIdx.y;
    int i0 = blockIdx.x * 32;
    int tid = threadIdx.x;
    int wid = tid >> 5, lane = tid & 31;
    int wm = wid >> 1, wn = wid & 1;
    int g = lane >> 2, t = lane & 3;
    const int ra = 16 * wm + g;
    const int rb = ra + 8;
    const int NU1 = wn ? 3 : 4;

    // ---- load Q tile ----
    const float* Qg = g_q + ((size_t)bh * N_ + i0) * HD_;
    #pragma unroll
    for (int it = 0; it < 6; it++) {
        int idx = tid + 128 * it;
        int r = idx / 24, c4 = idx % 24;
        *(float4*)&Qs[r * 96 + c4 * 4] = *(const float4*)&Qg[r * 96 + c4 * 4];
    }
    __syncthreads();

    // ---- hoist Q fragments to registers (tf32, pre-scaled by KSC_) ----
    unsigned qf[12][4];
    #pragma unroll
    for (int ks = 0; ks < 12; ks++) {
        int k0 = ks * 8;
        qf[ks][0] = cvt_tf32(Qs[ra * 96 + k0 + t] * KSC_);
        qf[ks][1] = cvt_tf32(Qs[rb * 96 + k0 + t] * KSC_);
        qf[ks][2] = cvt_tf32(Qs[ra * 96 + k0 + t + 4] * KSC_);
        qf[ks][3] = cvt_tf32(Qs[rb * 96 + k0 + t + 4] * KSC_);
    }

    // ---- rel-pos bias dots from Qs (x log2e) ----
    #pragma unroll
    for (int idx = tid; idx < 1152; idx += 128) {
        int r = idx / 36, e = idx - (idx / 36) * 36;
        int i = i0 + r;
        int it = i / 196;
        int rm = i - it * 196;
        int ih = rm / 14, iw = rm - ih * 14;
        const float* tab;
        float* dst;
        if (e < 14)      { tab = rph + (ih - e + 13) * HD_;        dst = &Rh[r * 14 + e]; }
        else if (e < 28) { int k = e - 14; tab = rpw + (iw - k + 13) * HD_; dst = &Rw[r * 14 + k]; }
        else             { int k = e - 28; tab = rpt + (it - k + 7) * HD_;  dst = &Rt[r * 8 + k]; }
        float s = 0.f;
        #pragma unroll 6
        for (int c4 = 0; c4 < 24; c4++) {
            float4 a = *(float4*)&Qs[r * 96 + c4 * 4];
            float4 b = *(const float4*)&tab[c4 * 4];
            s += a.x * b.x + a.y * b.y + a.z * b.z + a.w * b.w;
        }
        *dst = s * LOG2E_;
    }

    float lpA = 0.f, lpB = 0.f;
    float accO[6][4] = {};

    const float* Kg = g_k + (size_t)bh * N_ * HD_;
    const float* Vg = g_v + (size_t)bh * N_ * HD_;
    unsigned ks_base = (unsigned)__cvta_generic_to_shared(Ks);
    unsigned vs_base = (unsigned)__cvta_generic_to_shared(Vs);

    for (int ch = 0; ch < 28; ch++) {
        int j0 = ch * 56;
        __syncthreads();
        // ---- staging: 1344 x 16B cp.async copies (no cvt, no regs) ----
        #pragma unroll
        for (int it = 0; it < 11; it++) {
            int idx = tid + 128 * it;
            if (it == 10 && tid >= 64) break;
            int row = idx / 24, c4 = idx % 24;
            int j = j0 + row;
            cp_async16(ks_base + (row * 100 + c4 * 4) * 4, &Kg[(size_t)j * 96 + c4 * 4]);
            cp_async16(vs_base + (row * 104 + c4 * 4) * 4, &Vg[(size_t)j * 96 + c4 * 4]);
        }
        asm volatile("cp.async.commit_group;");
        asm volatile("cp.async.wait_group 0;" ::: "memory");
        __syncthreads();

        // ---- GEMM1: S = (Q*ksc) @ K^T, A-frags in registers ----
        float c[4][4] = {};
        #pragma unroll
        for (int ks = 0; ks < 12; ks++) {
            int k0 = ks * 8;
            #pragma unroll
            for (int u = 0; u < 4; u++) {
                if (u >= NU1) break;
                int kr = 32 * wn + 8 * u + g;
                unsigned b0 = Ks[kr * 100 + k0 + t];
                unsigned b1 = Ks[kr * 100 + k0 + t + 4];
                mma_tf32(c[u], qf[ks][0], qf[ks][1], qf[ks][2], qf[ks][3], b0, b1);
            }
        }

        // ---- bias + exp2; P stored tf32 (uint2) ----
        #pragma unroll
        for (int u = 0; u < 4; u++) {
            if (u >= NU1) break;
            int cc = 32 * wn + 8 * u + 2 * t;
            int j = j0 + cc;
            int jt0 = j / 196;         int jr0 = j - jt0 * 196;
            int jh0 = jr0 / 14;        int jw0 = jr0 - jh0 * 14;
            int j1 = j + 1;
            int jt1 = j1 / 196;        int jr1 = j1 - jt1 * 196;
            int jh1 = jr1 / 14;        int jw1 = jr1 - jh1 * 14;
            float pA0 = ex2f(c[u][0] + Rt[ra * 8 + jt0] + Rh[ra * 14 + jh0] + Rw[ra * 14 + jw0]);
            float pA1 = ex2f(c[u][1] + Rt[ra * 8 + jt1] + Rh[ra * 14 + jh1] + Rw[ra * 14 + jw1]);
            float pB0 = ex2f(c[u][2] + Rt[rb * 8 + jt0] + Rh[rb * 14 + jh0] + Rw[rb * 14 + jw0]);
            float pB1 = ex2f(c[u][3] + Rt[rb * 8 + jt1] + Rh[rb * 14 + jh1] + Rw[rb * 14 + jw1]);
            unsigned a0 = cvt_tf32(pA0), a1 = cvt_tf32(pA1);
            unsigned b0 = cvt_tf32(pB0), b1 = cvt_tf32(pB1);
            lpA += __uint_as_float(a0) + __uint_as_float(a1);
            lpB += __uint_as_float(b0) + __uint_as_float(b1);
            *(uint2*)&Ps[ra * 68 + cc] = make_uint2(a0, a1);
            *(uint2*)&Ps[rb * 68 + cc] = make_uint2(b0, b1);
        }
        __syncthreads();

        // ---- GEMM2: O += P @ V (B from row-major Vs, stride 104) ----
        #pragma unroll
        for (int ks = 0; ks < 7; ks++) {
            int k0 = ks * 8;
            unsigned a0 = Ps[ra * 68 + k0 + t];
            unsigned a1 = Ps[rb * 68 + k0 + t];
            unsigned a2 = Ps[ra * 68 + k0 + t + 4];
            unsigned a3 = Ps[rb * 68 + k0 + t + 4];
            #pragma unroll
            for (int u = 0; u < 6; u++) {
                int nr = 48 * wn + 8 * u + g;
                unsigned b0 = Vs[(k0 + t) * 104 + nr];
                unsigned b1 = Vs[(k0 + t + 4) * 104 + nr];
                mma_tf32(accO[u], a0, a1, a2, a3, b0, b1);
            }
        }
    }

    // ---- row-sum combine ----
    lpA += __shfl_xor_sync(0xffffffffu, lpA, 1);
    lpA += __shfl_xor_sync(0xffffffffu, lpA, 2);
    lpB += __shfl_xor_sync(0xffffffffu, lpB, 1);
    lpB += __shfl_xor_sync(0xffffffffu, lpB, 2);
    if (t == 0) {
        Ls[ra * 2 + wn] = lpA;
        Ls[rb * 2 + wn] = lpB;
    }
    __syncthreads();

    // ---- epilogue (MMA C layout): O/l + residual q -> g_ctx ----
    int b = bh >> 2, nh = bh & 3;
    #pragma unroll
    for (int half = 0; half < 2; half++) {
        int r = ra + 8 * half;
        int i = i0 + r;
        float inv = 1.f / (Ls[r * 2] + Ls[r * 2 + 1]);
        float* dst = &g_ctx[(((size_t)b * N_ + i) * NH_ + nh) * HD_];
        #pragma unroll
        for (int u = 0; u < 6; u++) {
            int cc = 48 * wn + 8 * u + 2 * t;
            float2 v;
            v.x = accO[u][2 * half]     * inv + Qs[r * 96 + cc];
            v.y = accO[u][2 * half + 1] * inv + Qs[r * 96 + cc + 1];
            *(float2*)&dst[cc] = v;
        }
    }
}

// ---------------- K4: output projection + bias (tf32 MMA) ------------------
__global__ void __launch_bounds__(256, 2) k_proj(const float* __restrict__ proj_w,
                                                 const float* __restrict__ proj_b,
                                                 float* __restrict__ out) {
    int n0 = blockIdx.x * 64, m0 = blockIdx.y * 64;
    int tid = threadIdx.x;
    int wid = tid >> 5, lane = tid & 31;
    int wm = wid >> 1, wn = wid & 1;
    int g = lane >> 2, t = lane & 3;
    float acc[4][4] = {};
    mma_nt64(g_ctx, proj_w, DIM_, m0, n0, wm, wn, g, t, tid, acc);

    int ra = 16 * wm + g;
    #pragma unroll
    for (int half = 0; half < 2; half++) {
        int m = m0 + ra + 8 * half;
        #pragma unroll
        for (int u = 0; u < 4; u++) {
            int o = n0 + 32 * wn + 8 * u + 2 * t;
            float2 v;
            v.x = acc[u][2 * half]     + proj_b[o];
            v.y = acc[u][2 * half + 1] + proj_b[o + 1];
            *(float2*)&out[(size_t)m * DIM_ + o] = v;
        }
    }
}

// ---------------- launch ----------------------------------------------------
extern "C" void kernel_launch(void* const* d_in, const int* in_sizes, int n_in,
                              void* d_out, int out_size) {
    const float* x      = (const float*)d_in[0];
    const float* qkv_w  = (const float*)d_in[1];
    const float* proj_w = (const float*)d_in[2];
    const float* proj_b = (const float*)d_in[3];
    const float* pqw    = (const float*)d_in[4];
    const float* pkw    = (const float*)d_in[5];
    const float* pvw    = (const float*)d_in[6];
    const float* nqw    = (const float*)d_in[7];
    const float* nqb    = (const float*)d_in[8];
    const float* nkw    = (const float*)d_in[9];
    const float* nkb    = (const float*)d_in[10];
    const float* nvw    = (const float*)d_in[11];
    const float* nvb    = (const float*)d_in[12];
    const float* rph    = (const float*)d_in[13];
    const float* rpw    = (const float*)d_in[14];
    const float* rpt    = (const float*)d_in[15];
    float* out = (float*)d_out;

    cudaFuncSetAttribute(k_flash, cudaFuncAttributeMaxDynamicSharedMemorySize, 71552);

    k_qkv<<<dim3(18, 49), 256>>>(x, qkv_w);
    k_conv_ln<<<(BH_ * N_ * 3) / 4, 128>>>(pqw, pkw, pvw, nqw, nqb, nkw, nkb, nvw, nvb);
    k_flash<<<dim3(49, BH_), 128, 71552>>>(rph, rpw, rpt);
    k_proj<<<dim3(6, 49), 256>>>(proj_w, proj_b, out);
}